// round 13
// baseline (speedup 1.0000x reference)
#include <cuda_runtime.h>
#include <cstdint>

#define NB      32768
#define DIN     784
#define DH      512
#define DOUT    10
#define NSTEPS  25
#define BETA    0.9f
#define THR     1.0f
#define TB      5
#define NTB     (NSTEPS / TB)

typedef unsigned long long u64;

// ---------------- static device scratch ----------------
__device__ float g_cur1[(size_t)NB * DH];

// ---------------- f32x2 helpers (sm_100+ family PTX) ----------------
__device__ __forceinline__ u64 pack2(float lo, float hi) {
    u64 r; asm("mov.b64 %0, {%1, %2};" : "=l"(r) : "f"(lo), "f"(hi)); return r;
}
__device__ __forceinline__ void unpack2(u64 v, float& lo, float& hi) {
    asm("mov.b64 {%0, %1}, %2;" : "=f"(lo), "=f"(hi) : "l"(v));
}
__device__ __forceinline__ u64 fma2(u64 a, u64 b, u64 c) {
    u64 d; asm("fma.rn.f32x2 %0, %1, %2, %3;" : "=l"(d) : "l"(a), "l"(b), "l"(c)); return d;
}
__device__ __forceinline__ u64 add2(u64 a, u64 b) {
    u64 d; asm("add.rn.f32x2 %0, %1, %2;" : "=l"(d) : "l"(a), "l"(b)); return d;
}

// ---------------------------------------------------------------------------
// GEMM via packed f32x2 FFMA. fma2-PIPE-bound (R12 analysis), so the only
// lever is wave quantization: tile 64x256, 128 threads/CTA, SAME 8x16
// per-warp micro-tile and inner loop as the measured-best R9 kernel.
// 3 CTAs/SM resident (regs ~170 -> 21.8K/CTA; smem 42KB/CTA) -> 1024 fine
// tiles pack the SMs far better than 512 coarse ones (model 700K vs 800K
// SM-cycles). Per-output FFMA2 chain unchanged (sequential k, bias last)
// -> bit-identical to all passing rounds.
// ---------------------------------------------------------------------------
#define BM 64
#define BN 256
#define BK 16
#define GNKT (DIN / BK)       // 49
#define ARS 68                // A smem row stride (floats)
#define BRS 260               // B smem row stride (floats)
#define SMEM_GEMM ((2 * BK * ARS + 2 * BK * BRS) * 4)   // 41984 B

__global__ void __launch_bounds__(128, 3)
gemm1_f32x2(const float* __restrict__ X,
            const float* __restrict__ W1,
            const float* __restrict__ b1)
{
    extern __shared__ float sm[];
    float (*As)[BK][ARS] = (float (*)[BK][ARS])sm;
    float (*Bs)[BK][BRS] = (float (*)[BK][BRS])(sm + 2 * BK * ARS);

    const int tid = threadIdx.x;
    const int bm = blockIdx.y * BM;
    const int bn = blockIdx.x * BN;
    const int ty = tid >> 4;          // 0..7  (m: 4+4 rows, stride 32)
    const int tx = tid & 15;          // 0..15 (n: 4x4 cols, stride 64)

    // loaders: A = 1 row (2 float4), B = 2 rows (4 float4 each)
    const int lmA = tid >> 1, lkA = (tid & 1) * 8;
    const float* aptr  = X  + (size_t)(bm + lmA) * DIN + lkA;
    const float* bptr0 = W1 + (size_t)(bn + tid) * DIN;
    const float* bptr1 = W1 + (size_t)(bn + 128 + tid) * DIN;

    float4 fa0, fa1, fb[8];
    fa0 = *(const float4*)(aptr);
    fa1 = *(const float4*)(aptr + 4);
    #pragma unroll
    for (int h = 0; h < 4; h++) {
        fb[h]     = *(const float4*)(bptr0 + h * 4);
        fb[4 + h] = *(const float4*)(bptr1 + h * 4);
    }
    #pragma unroll
    for (int q = 0; q < 4; q++) {
        As[0][lkA + q][lmA]     = ((const float*)&fa0)[q];
        As[0][lkA + 4 + q][lmA] = ((const float*)&fa1)[q];
        #pragma unroll
        for (int h = 0; h < 4; h++) {
            Bs[0][h * 4 + q][tid]       = ((const float*)&fb[h])[q];
            Bs[0][h * 4 + q][128 + tid] = ((const float*)&fb[4 + h])[q];
        }
    }
    __syncthreads();

    u64 acc[8][8];
    #pragma unroll
    for (int i = 0; i < 8; i++)
        #pragma unroll
        for (int p = 0; p < 8; p++) acc[i][p] = 0ULL;

    for (int kt = 0; kt < GNKT; kt++) {
        const int buf = kt & 1;
        if (kt + 1 < GNKT) {
            const int ko = (kt + 1) * BK;
            fa0 = *(const float4*)(aptr + ko);
            fa1 = *(const float4*)(aptr + ko + 4);
            #pragma unroll
            for (int h = 0; h < 4; h++) {
                fb[h]     = *(const float4*)(bptr0 + ko + h * 4);
                fb[4 + h] = *(const float4*)(bptr1 + ko + h * 4);
            }
        }
        #pragma unroll
        for (int k = 0; k < BK; k++) {
            const float4 av0 = *(const float4*)(&As[buf][k][ty * 4]);
            const float4 av1 = *(const float4*)(&As[buf][k][ty * 4 + 32]);
            u64 b2v[8];
            #pragma unroll
            for (int c = 0; c < 4; c++) {
                const ulonglong2 bv = *(const ulonglong2*)(&Bs[buf][k][tx * 4 + c * 64]);
                b2v[c * 2]     = bv.x;
                b2v[c * 2 + 1] = bv.y;
            }
            const float a[8] = {av0.x, av0.y, av0.z, av0.w, av1.x, av1.y, av1.z, av1.w};
            #pragma unroll
            for (int i = 0; i < 8; i++) {
                const u64 a2 = pack2(a[i], a[i]);
                #pragma unroll
                for (int p = 0; p < 8; p++)
                    acc[i][p] = fma2(a2, b2v[p], acc[i][p]);
            }
        }
        if (kt + 1 < GNKT) {
            const int nb = buf ^ 1;
            #pragma unroll
            for (int q = 0; q < 4; q++) {
                As[nb][lkA + q][lmA]     = ((const float*)&fa0)[q];
                As[nb][lkA + 4 + q][lmA] = ((const float*)&fa1)[q];
                #pragma unroll
                for (int h = 0; h < 4; h++) {
                    Bs[nb][h * 4 + q][tid]       = ((const float*)&fb[h])[q];
                    Bs[nb][h * 4 + q][128 + tid] = ((const float*)&fb[4 + h])[q];
                }
            }
        }
        __syncthreads();
    }

    float4 bias[4];
    #pragma unroll
    for (int c = 0; c < 4; c++)
        bias[c] = __ldg((const float4*)(b1 + bn + tx * 4 + c * 64));

    #pragma unroll
    for (int i = 0; i < 8; i++) {
        const int m = bm + ty * 4 + (i >> 2) * 32 + (i & 3);
        float* orow = g_cur1 + (size_t)m * DH + bn + tx * 4;
        #pragma unroll
        for (int c = 0; c < 4; c++) {
            float v0, v1, v2, v3;
            unpack2(acc[i][c * 2],     v0, v1);
            unpack2(acc[i][c * 2 + 1], v2, v3);
            float4 v = {v0 + bias[c].x, v1 + bias[c].y, v2 + bias[c].z, v3 + bias[c].w};
            *(float4*)(orow + c * 64) = v;
        }
    }
}

// ---------------------------------------------------------------------------
// Fused 25-step SNN — EXACT R10 version (measured 240us x3 rounds).
// ---------------------------------------------------------------------------
#define WTS 12
#define SPK1 0x3F8000003F800000ULL   // (1.0f, 1.0f)

__global__ __launch_bounds__(256, 2)
void snn_kernel(const float* __restrict__ W2,
                const float* __restrict__ b2,
                float* __restrict__ out)
{
    __shared__ __align__(16) float w2t[DH][WTS];   // 24 KB, W2 transposed
    for (int idx = threadIdx.x; idx < DOUT * DH; idx += 256) {
        const int j = idx / DH, n = idx % DH;
        w2t[n][j] = W2[idx];
    }
    __syncthreads();

    const int warp = threadIdx.x >> 5;
    const int lane = threadIdx.x & 31;
    const int row  = blockIdx.x * 8 + warp;

    float cur1[16], mem1[16];
    const float* cr = g_cur1 + (size_t)row * DH + lane;
    #pragma unroll
    for (int i = 0; i < 16; i++) {
        cur1[i] = cr[i * 32];
        mem1[i] = 0.f;
    }

    float mem2 = 0.f;
    const float b2v = (lane < DOUT) ? b2[lane] : 0.f;
    const size_t MEMOFF = (size_t)NSTEPS * NB * DOUT;
    const int cidx = (lane >> 1) > 4 ? 4 : (lane >> 1);

    for (int tb = 0; tb < NTB; tb++) {
        u64 V[25];
        #pragma unroll
        for (int v = 0; v < 25; v++) V[v] = 0ULL;

        #pragma unroll
        for (int i = 0; i < 16; i++) {
            const float* wr = &w2t[i * 32 + lane][0];
            const ulonglong2 w01 = *(const ulonglong2*)(wr);
            const ulonglong2 w23 = *(const ulonglong2*)(wr + 4);
            const u64        w4  = *(const u64*)(wr + 8);

            float m = mem1[i];
            const float c1 = cur1[i];
            #pragma unroll
            for (int tt = 0; tt < TB; tt++) {
                const bool p0 = m > THR;
                m = fmaf(BETA, m, c1);
                if (p0) m = m - THR;
                const u64 s2 = (m > THR) ? SPK1 : 0ULL;
                V[tt * 5 + 0] = fma2(s2, w01.x, V[tt * 5 + 0]);
                V[tt * 5 + 1] = fma2(s2, w01.y, V[tt * 5 + 1]);
                V[tt * 5 + 2] = fma2(s2, w23.x, V[tt * 5 + 2]);
                V[tt * 5 + 3] = fma2(s2, w23.y, V[tt * 5 + 3]);
                V[tt * 5 + 4] = fma2(s2, w4,    V[tt * 5 + 4]);
            }
            mem1[i] = m;
        }

        // reduce-scatter (same tree as butterfly -> bit-identical)
        {
            const bool h = (lane & 16) != 0;
            #pragma unroll
            for (int s = 0; s < 16; s++) {
                const u64 lo = V[s];
                const u64 hi = (s + 16 < 25) ? V[s + 16] : 0ULL;
                const u64 snd  = h ? lo : hi;
                const u64 rcv  = __shfl_xor_sync(0xffffffffu, snd, 16);
                const u64 kept = h ? hi : lo;
                V[s] = add2(kept, rcv);
            }
        }
        {
            const bool h = (lane & 8) != 0;
            #pragma unroll
            for (int s = 0; s < 8; s++) {
                const u64 snd  = h ? V[s] : V[s + 8];
                const u64 rcv  = __shfl_xor_sync(0xffffffffu, snd, 8);
                const u64 kept = h ? V[s + 8] : V[s];
                V[s] = add2(kept, rcv);
            }
        }
        {
            const bool h = (lane & 4) != 0;
            #pragma unroll
            for (int s = 0; s < 4; s++) {
                const u64 snd  = h ? V[s] : V[s + 4];
                const u64 rcv  = __shfl_xor_sync(0xffffffffu, snd, 4);
                const u64 kept = h ? V[s + 4] : V[s];
                V[s] = add2(kept, rcv);
            }
        }
        {
            const bool h = (lane & 2) != 0;
            #pragma unroll
            for (int s = 0; s < 2; s++) {
                const u64 snd  = h ? V[s] : V[s + 2];
                const u64 rcv  = __shfl_xor_sync(0xffffffffu, snd, 2);
                const u64 kept = h ? V[s + 2] : V[s];
                V[s] = add2(kept, rcv);
            }
        }
        {
            const bool h = (lane & 1) != 0;
            const u64 snd  = h ? V[0] : V[1];
            const u64 rcv  = __shfl_xor_sync(0xffffffffu, snd, 1);
            const u64 kept = h ? V[1] : V[0];
            V[0] = add2(kept, rcv);
        }

        #pragma unroll
        for (int tt = 0; tt < TB; tt++) {
            const u64 g = __shfl_sync(0xffffffffu, V[0], tt * 5 + cidx);
            if (lane < DOUT) {
                float gLo, gHi;
                unpack2(g, gLo, gHi);
                const float p = (lane & 1) ? gHi : gLo;

                const float c2 = p + b2v;
                const float nm = BETA * mem2 + c2 - ((mem2 > THR) ? THR : 0.f);
                mem2 = nm;

                const int t = tb * TB + tt;
                const size_t base = (size_t)t * NB * DOUT + (size_t)row * DOUT + lane;
                out[base]          = (nm > THR) ? 1.f : 0.f;
                out[MEMOFF + base] = nm;
            }
        }
    }
}

// ---------------------------------------------------------------------------
extern "C" void kernel_launch(void* const* d_in, const int* in_sizes, int n_in,
                              void* d_out, int out_size)
{
    (void)in_sizes; (void)n_in; (void)out_size;
    const float* x  = (const float*)d_in[0];   // [32768, 784]
    const float* W1 = (const float*)d_in[1];   // [512, 784]
    const float* b1 = (const float*)d_in[2];   // [512]
    const float* W2 = (const float*)d_in[3];   // [10, 512]
    const float* b2 = (const float*)d_in[4];   // [10]
    float* out = (float*)d_out;                // [2, 25, 32768, 10]

    cudaFuncSetAttribute(gemm1_f32x2, cudaFuncAttributeMaxDynamicSharedMemorySize, SMEM_GEMM);
    dim3 ggrid(DH / BN, NB / BM);              // (2, 512) = 1024 CTAs
    gemm1_f32x2<<<ggrid, 128, SMEM_GEMM>>>(x, W1, b1);

    snn_kernel<<<NB / 8, 256>>>(W2, b2, out);  // 8 warps x 1 row
}

// round 14
// speedup vs baseline: 1.4370x; 1.4370x over previous
#include <cuda_runtime.h>
#include <cstdint>

#define NB      32768
#define DIN     784
#define DH      512
#define DOUT    10
#define NSTEPS  25
#define BETA    0.9f
#define THR     1.0f
#define TB      5
#define NTB     (NSTEPS / TB)

#define NCHUNK  4
#define CROWS   (NB / NCHUNK)      // 8192 rows per chunk

typedef unsigned long long u64;

// ---------------- static device scratch ----------------
__device__ float g_cur1[(size_t)NB * DH];

// ---------------- f32x2 helpers (sm_100+ family PTX) ----------------
__device__ __forceinline__ u64 pack2(float lo, float hi) {
    u64 r; asm("mov.b64 %0, {%1, %2};" : "=l"(r) : "f"(lo), "f"(hi)); return r;
}
__device__ __forceinline__ void unpack2(u64 v, float& lo, float& hi) {
    asm("mov.b64 {%0, %1}, %2;" : "=f"(lo), "=f"(hi) : "l"(v));
}
__device__ __forceinline__ u64 fma2(u64 a, u64 b, u64 c) {
    u64 d; asm("fma.rn.f32x2 %0, %1, %2, %3;" : "=l"(d) : "l"(a), "l"(b), "l"(c)); return d;
}
__device__ __forceinline__ u64 add2(u64 a, u64 b) {
    u64 d; asm("add.rn.f32x2 %0, %1, %2;" : "=l"(d) : "l"(a), "l"(b)); return d;
}

// ---------------------------------------------------------------------------
// GEMM via packed f32x2 FFMA — EXACT R9 kernel (best measured ~510us) plus a
// row-base offset so it can be launched per 8192-row chunk. Which CTA
// computes which row is irrelevant to the FFMA2 chain -> bit-identical.
// ---------------------------------------------------------------------------
#define BM 128
#define BN 256
#define BK 16
#define GNKT (DIN / BK)       // 49
#define ARS 132
#define BRS 260
#define SMEM_GEMM ((2 * BK * ARS + 2 * BK * BRS) * 4)   // 50176 B

__global__ void __launch_bounds__(256, 1)
gemm1_f32x2(const float* __restrict__ X,
            const float* __restrict__ W1,
            const float* __restrict__ b1,
            int mBase)
{
    extern __shared__ float sm[];
    float (*As)[BK][ARS] = (float (*)[BK][ARS])sm;
    float (*Bs)[BK][BRS] = (float (*)[BK][BRS])(sm + 2 * BK * ARS);

    const int tid = threadIdx.x;
    const int bm = mBase + blockIdx.y * BM;
    const int bn = blockIdx.x * BN;
    const int ty = tid >> 4;
    const int tx = tid & 15;

    const int lmA = tid >> 1, lkA = (tid & 1) * 8;
    const int lmB = tid;
    const float* aptr = X  + (size_t)(bm + lmA) * DIN + lkA;
    const float* bptr = W1 + (size_t)(bn + lmB) * DIN;

    float4 fa0, fa1, fb0, fb1, fb2, fb3;
    fa0 = *(const float4*)(aptr);
    fa1 = *(const float4*)(aptr + 4);
    fb0 = *(const float4*)(bptr);
    fb1 = *(const float4*)(bptr + 4);
    fb2 = *(const float4*)(bptr + 8);
    fb3 = *(const float4*)(bptr + 12);
    #pragma unroll
    for (int q = 0; q < 4; q++) {
        As[0][lkA + q][lmA]     = ((const float*)&fa0)[q];
        As[0][lkA + 4 + q][lmA] = ((const float*)&fa1)[q];
        Bs[0][q][lmB]      = ((const float*)&fb0)[q];
        Bs[0][4 + q][lmB]  = ((const float*)&fb1)[q];
        Bs[0][8 + q][lmB]  = ((const float*)&fb2)[q];
        Bs[0][12 + q][lmB] = ((const float*)&fb3)[q];
    }
    __syncthreads();

    u64 acc[8][8];
    #pragma unroll
    for (int i = 0; i < 8; i++)
        #pragma unroll
        for (int p = 0; p < 8; p++) acc[i][p] = 0ULL;

    for (int kt = 0; kt < GNKT; kt++) {
        const int buf = kt & 1;
        if (kt + 1 < GNKT) {
            const float* ap = aptr + (kt + 1) * BK;
            const float* bp = bptr + (kt + 1) * BK;
            fa0 = *(const float4*)(ap);
            fa1 = *(const float4*)(ap + 4);
            fb0 = *(const float4*)(bp);
            fb1 = *(const float4*)(bp + 4);
            fb2 = *(const float4*)(bp + 8);
            fb3 = *(const float4*)(bp + 12);
        }
        #pragma unroll
        for (int k = 0; k < BK; k++) {
            const float4 av0 = *(const float4*)(&As[buf][k][ty * 4]);
            const float4 av1 = *(const float4*)(&As[buf][k][ty * 4 + 64]);
            u64 b2v[8];
            #pragma unroll
            for (int c = 0; c < 4; c++) {
                const ulonglong2 bv = *(const ulonglong2*)(&Bs[buf][k][tx * 4 + c * 64]);
                b2v[c * 2]     = bv.x;
                b2v[c * 2 + 1] = bv.y;
            }
            const float a[8] = {av0.x, av0.y, av0.z, av0.w, av1.x, av1.y, av1.z, av1.w};
            #pragma unroll
            for (int i = 0; i < 8; i++) {
                const u64 a2 = pack2(a[i], a[i]);
                #pragma unroll
                for (int p = 0; p < 8; p++)
                    acc[i][p] = fma2(a2, b2v[p], acc[i][p]);
            }
        }
        if (kt + 1 < GNKT) {
            const int nb = buf ^ 1;
            #pragma unroll
            for (int q = 0; q < 4; q++) {
                As[nb][lkA + q][lmA]     = ((const float*)&fa0)[q];
                As[nb][lkA + 4 + q][lmA] = ((const float*)&fa1)[q];
                Bs[nb][q][lmB]      = ((const float*)&fb0)[q];
                Bs[nb][4 + q][lmB]  = ((const float*)&fb1)[q];
                Bs[nb][8 + q][lmB]  = ((const float*)&fb2)[q];
                Bs[nb][12 + q][lmB] = ((const float*)&fb3)[q];
            }
        }
        __syncthreads();
    }

    float4 bias[4];
    #pragma unroll
    for (int c = 0; c < 4; c++)
        bias[c] = __ldg((const float4*)(b1 + bn + tx * 4 + c * 64));

    #pragma unroll
    for (int i = 0; i < 8; i++) {
        const int m = bm + ty * 4 + (i >> 2) * 64 + (i & 3);
        float* orow = g_cur1 + (size_t)m * DH + bn + tx * 4;
        #pragma unroll
        for (int c = 0; c < 4; c++) {
            float v0, v1, v2, v3;
            unpack2(acc[i][c * 2],     v0, v1);
            unpack2(acc[i][c * 2 + 1], v2, v3);
            float4 v = {v0 + bias[c].x, v1 + bias[c].y, v2 + bias[c].z, v3 + bias[c].w};
            *(float4*)(orow + c * 64) = v;
        }
    }
}

// ---------------------------------------------------------------------------
// Fused 25-step SNN — EXACT R10 kernel (measured 240us x4 rounds) plus a
// row-base offset for chunked launches. Bit-identical per row.
// ---------------------------------------------------------------------------
#define WTS 12
#define SPK1 0x3F8000003F800000ULL   // (1.0f, 1.0f)

__global__ __launch_bounds__(256, 2)
void snn_kernel(const float* __restrict__ W2,
                const float* __restrict__ b2,
                float* __restrict__ out,
                int rowBase)
{
    __shared__ __align__(16) float w2t[DH][WTS];   // 24 KB, W2 transposed
    for (int idx = threadIdx.x; idx < DOUT * DH; idx += 256) {
        const int j = idx / DH, n = idx % DH;
        w2t[n][j] = W2[idx];
    }
    __syncthreads();

    const int warp = threadIdx.x >> 5;
    const int lane = threadIdx.x & 31;
    const int row  = rowBase + blockIdx.x * 8 + warp;

    float cur1[16], mem1[16];
    const float* cr = g_cur1 + (size_t)row * DH + lane;
    #pragma unroll
    for (int i = 0; i < 16; i++) {
        cur1[i] = cr[i * 32];
        mem1[i] = 0.f;
    }

    float mem2 = 0.f;
    const float b2v = (lane < DOUT) ? b2[lane] : 0.f;
    const size_t MEMOFF = (size_t)NSTEPS * NB * DOUT;
    const int cidx = (lane >> 1) > 4 ? 4 : (lane >> 1);

    for (int tb = 0; tb < NTB; tb++) {
        u64 V[25];
        #pragma unroll
        for (int v = 0; v < 25; v++) V[v] = 0ULL;

        #pragma unroll
        for (int i = 0; i < 16; i++) {
            const float* wr = &w2t[i * 32 + lane][0];
            const ulonglong2 w01 = *(const ulonglong2*)(wr);
            const ulonglong2 w23 = *(const ulonglong2*)(wr + 4);
            const u64        w4  = *(const u64*)(wr + 8);

            float m = mem1[i];
            const float c1 = cur1[i];
            #pragma unroll
            for (int tt = 0; tt < TB; tt++) {
                const bool p0 = m > THR;
                m = fmaf(BETA, m, c1);
                if (p0) m = m - THR;
                const u64 s2 = (m > THR) ? SPK1 : 0ULL;
                V[tt * 5 + 0] = fma2(s2, w01.x, V[tt * 5 + 0]);
                V[tt * 5 + 1] = fma2(s2, w01.y, V[tt * 5 + 1]);
                V[tt * 5 + 2] = fma2(s2, w23.x, V[tt * 5 + 2]);
                V[tt * 5 + 3] = fma2(s2, w23.y, V[tt * 5 + 3]);
                V[tt * 5 + 4] = fma2(s2, w4,    V[tt * 5 + 4]);
            }
            mem1[i] = m;
        }

        // reduce-scatter (same tree as butterfly -> bit-identical)
        {
            const bool h = (lane & 16) != 0;
            #pragma unroll
            for (int s = 0; s < 16; s++) {
                const u64 lo = V[s];
                const u64 hi = (s + 16 < 25) ? V[s + 16] : 0ULL;
                const u64 snd  = h ? lo : hi;
                const u64 rcv  = __shfl_xor_sync(0xffffffffu, snd, 16);
                const u64 kept = h ? hi : lo;
                V[s] = add2(kept, rcv);
            }
        }
        {
            const bool h = (lane & 8) != 0;
            #pragma unroll
            for (int s = 0; s < 8; s++) {
                const u64 snd  = h ? V[s] : V[s + 8];
                const u64 rcv  = __shfl_xor_sync(0xffffffffu, snd, 8);
                const u64 kept = h ? V[s + 8] : V[s];
                V[s] = add2(kept, rcv);
            }
        }
        {
            const bool h = (lane & 4) != 0;
            #pragma unroll
            for (int s = 0; s < 4; s++) {
                const u64 snd  = h ? V[s] : V[s + 4];
                const u64 rcv  = __shfl_xor_sync(0xffffffffu, snd, 4);
                const u64 kept = h ? V[s + 4] : V[s];
                V[s] = add2(kept, rcv);
            }
        }
        {
            const bool h = (lane & 2) != 0;
            #pragma unroll
            for (int s = 0; s < 2; s++) {
                const u64 snd  = h ? V[s] : V[s + 2];
                const u64 rcv  = __shfl_xor_sync(0xffffffffu, snd, 2);
                const u64 kept = h ? V[s + 2] : V[s];
                V[s] = add2(kept, rcv);
            }
        }
        {
            const bool h = (lane & 1) != 0;
            const u64 snd  = h ? V[0] : V[1];
            const u64 rcv  = __shfl_xor_sync(0xffffffffu, snd, 1);
            const u64 kept = h ? V[1] : V[0];
            V[0] = add2(kept, rcv);
        }

        #pragma unroll
        for (int tt = 0; tt < TB; tt++) {
            const u64 g = __shfl_sync(0xffffffffu, V[0], tt * 5 + cidx);
            if (lane < DOUT) {
                float gLo, gHi;
                unpack2(g, gLo, gHi);
                const float p = (lane & 1) ? gHi : gLo;

                const float c2 = p + b2v;
                const float nm = BETA * mem2 + c2 - ((mem2 > THR) ? THR : 0.f);
                mem2 = nm;

                const int t = tb * TB + tt;
                const size_t base = (size_t)t * NB * DOUT + (size_t)row * DOUT + lane;
                out[base]          = (nm > THR) ? 1.f : 0.f;
                out[MEMOFF + base] = nm;
            }
        }
    }
}

// ---------------------------------------------------------------------------
// Launch: 4 row-chunks pipelined on two streams. gemm_c on the capture
// (default) stream; snn_c on s2 gated by an event recorded after gemm_c.
// Join s2 back into the default stream at the end so the graph sink is
// correct. Streams/events created once, never destroyed (no device-mem
// allocation involved).
// ---------------------------------------------------------------------------
extern "C" void kernel_launch(void* const* d_in, const int* in_sizes, int n_in,
                              void* d_out, int out_size)
{
    (void)in_sizes; (void)n_in; (void)out_size;
    const float* x  = (const float*)d_in[0];   // [32768, 784]
    const float* W1 = (const float*)d_in[1];   // [512, 784]
    const float* b1 = (const float*)d_in[2];   // [512]
    const float* W2 = (const float*)d_in[3];   // [10, 512]
    const float* b2 = (const float*)d_in[4];   // [10]
    float* out = (float*)d_out;                // [2, 25, 32768, 10]

    static cudaStream_t s2 = nullptr;
    static cudaEvent_t evg[NCHUNK];
    static cudaEvent_t evf = nullptr;
    static bool init_done = false;
    if (!init_done) {
        cudaStreamCreateWithFlags(&s2, cudaStreamNonBlocking);
        for (int c = 0; c < NCHUNK; c++)
            cudaEventCreateWithFlags(&evg[c], cudaEventDisableTiming);
        cudaEventCreateWithFlags(&evf, cudaEventDisableTiming);
        cudaFuncSetAttribute(gemm1_f32x2,
                             cudaFuncAttributeMaxDynamicSharedMemorySize, SMEM_GEMM);
        init_done = true;
    }

    // gemm chunks on the default (capture) stream
    dim3 ggrid(DH / BN, CROWS / BM);           // (2, 64) per chunk
    for (int c = 0; c < NCHUNK; c++) {
        gemm1_f32x2<<<ggrid, 256, SMEM_GEMM>>>(x, W1, b1, c * CROWS);
        cudaEventRecord(evg[c], 0);
    }

    // snn chunks on s2, each gated on its gemm chunk
    for (int c = 0; c < NCHUNK; c++) {
        cudaStreamWaitEvent(s2, evg[c], 0);
        snn_kernel<<<CROWS / 8, 256, 0, s2>>>(W2, b2, out, c * CROWS);
    }

    // join s2 back into the default stream
    cudaEventRecord(evf, s2);
    cudaStreamWaitEvent(0, evf, 0);
}